// round 15
// baseline (speedup 1.0000x reference)
#include <cuda_runtime.h>
#include <cuda_fp16.h>
#include <math.h>
#include <stdint.h>

#define Nn   2048
#define Dd   256
#define DHd  64
#define ROWS 8192
#define HALF  (ROWS*Dd)
#define HHALF (ROWS*512)

// ---------------- scratch ----------------
__device__ __half g_xh [2*ROWS*Dd];
__device__ __half g_qkh[2*ROWS*Dd];
__device__ __half g_vh [2*ROWS*Dd];
__device__ float  g_m  [2*ROWS*Dd];     // attention output (fp32)
__device__ float  g_h  [2*ROWS*512];
__device__ float  g_a  [2*ROWS*512];
__device__ __half g_wh [2*65536];       // Wqk, Wv in fp16
__device__ float  g_wf [256*512];       // Wfused = Wo @ W1_bot
__device__ float  g_b1p[512];           // b1 + bo @ W1_bot
__device__ float  g_zero[512];          // zero bias (never written)

// ---------------- helpers ----------------
__device__ __forceinline__ uint32_t packh(float lo, float hi) {
    __half2 h = __floats2half2_rn(lo, hi);
    return *reinterpret_cast<uint32_t*>(&h);
}
__device__ __forceinline__ uint32_t su32(const void* p) {
    return (uint32_t)__cvta_generic_to_shared(p);
}
__device__ __forceinline__ void cpa16(void* dst, const void* src) {
    asm volatile("cp.async.cg.shared.global [%0], [%1], 16;"
                 :: "r"(su32(dst)), "l"(src));
}
__device__ __forceinline__ void cp_commit() {
    asm volatile("cp.async.commit_group;");
}
template <int N> __device__ __forceinline__ void cp_wait() {
    asm volatile("cp.async.wait_group %0;" :: "n"(N));
}

#define LDSM4(r, addr) \
    asm volatile("ldmatrix.sync.aligned.m8n8.x4.shared.b16 {%0,%1,%2,%3}, [%4];" \
                 : "=r"((r)[0]), "=r"((r)[1]), "=r"((r)[2]), "=r"((r)[3]) \
                 : "r"(addr))
#define LDSM4T(r, addr) \
    asm volatile("ldmatrix.sync.aligned.m8n8.x4.trans.shared.b16 {%0,%1,%2,%3}, [%4];" \
                 : "=r"((r)[0]), "=r"((r)[1]), "=r"((r)[2]), "=r"((r)[3]) \
                 : "r"(addr))

#define MMA_F16(c, a, b) \
    asm volatile("mma.sync.aligned.m16n8k16.row.col.f32.f16.f16.f32 " \
                 "{%0,%1,%2,%3},{%4,%5,%6,%7},{%8,%9},{%0,%1,%2,%3};" \
                 : "+f"((c)[0]), "+f"((c)[1]), "+f"((c)[2]), "+f"((c)[3]) \
                 : "r"((a)[0]), "r"((a)[1]), "r"((a)[2]), "r"((a)[3]), \
                   "r"((b)[0]), "r"((b)[1]))

#define MMA_TF32(c, a, b) \
    asm volatile("mma.sync.aligned.m16n8k8.row.col.f32.tf32.tf32.f32 " \
                 "{%0,%1,%2,%3},{%4,%5,%6,%7},{%8,%9},{%0,%1,%2,%3};" \
                 : "+f"((c)[0]), "+f"((c)[1]), "+f"((c)[2]), "+f"((c)[3]) \
                 : "r"((a)[0]), "r"((a)[1]), "r"((a)[2]), "r"((a)[3]), \
                   "r"((b)[0]), "r"((b)[1]))

// ---------------- fused fp32 -> fp16 conversion (x pair + 2 weights) -----
__global__ void __launch_bounds__(256) cvt_all(
    const float* __restrict__ x0, const float* __restrict__ x1,
    const float* __restrict__ w0, const float* __restrict__ w1,
    __half* __restrict__ xdst, __half* __restrict__ wdst)
{
    int i = (blockIdx.x * 256 + threadIdx.x) * 4;
    const float* src;
    __half* dst;
    int j;
    if (i < HALF)           { src = x0; j = i;        dst = xdst + i; }
    else if (i < 2*HALF)    { src = x1; j = i - HALF; dst = xdst + i; }
    else {
        int k = i - 2*HALF;
        dst = wdst + k;
        if (k < 65536)      { src = w0; j = k; }
        else                { src = w1; j = k - 65536; }
    }
    float4 v = *reinterpret_cast<const float4*>(src + j);
    uint2 u;
    u.x = packh(v.x, v.y);
    u.y = packh(v.z, v.w);
    *reinterpret_cast<uint2*>(dst) = u;
}

// ---------------- bias fold: b1p = b1 + bo @ W1_bot ----------------------
__global__ void __launch_bounds__(256) biasfold(
    const float* __restrict__ b1, const float* __restrict__ bo,
    const float* __restrict__ W1, float* __restrict__ b1p)
{
    int n = blockIdx.x * 256 + threadIdx.x;
    float s = b1[n];
    for (int k = 0; k < 256; k++)
        s += bo[k] * W1[(size_t)(256 + k)*512 + n];
    b1p[n] = s;
}

// ---------------- fp16 GEMM (validated; qk/v projections) ----------------
__global__ void __launch_bounds__(256, 2) gemm_hc(
    const __half* __restrict__ Alo, const __half* __restrict__ Ahi, int lda,
    const __half* __restrict__ Wa, const float* __restrict__ biasa,
    __half* __restrict__ Ca, float scalea,
    const __half* __restrict__ Wb, const float* __restrict__ biasb,
    __half* __restrict__ Cb, float scaleb,
    int N, int K)
{
    extern __shared__ __half smh[];

    const __half* W   = blockIdx.z ? Wb : Wa;
    const float* bias = blockIdx.z ? biasb : biasa;
    __half* C         = blockIdx.z ? Cb : Ca;
    const float scale = blockIdx.z ? scaleb : scalea;

    const int tile_n = blockIdx.x * 128;
    const int tile_m = blockIdx.y * 128;
    const int t = threadIdx.x;
    const int wid = t >> 5, lane = t & 31;
    const int wm = (wid >> 1) * 32, wn = (wid & 1) * 64;
    const int r = lane >> 2, c = lane & 3;

    const bool mhi = tile_m >= 8192;
    const __half* A1 = mhi ? Ahi : Alo;
    const int mloc = mhi ? tile_m - 8192 : tile_m;

    const uint32_t sbase = su32(smh);
    const int b_lane = ((lane & 15)*136 + ((lane >> 4) & 1)*8 + wn) * 2;

    float acc[2][8][4];
    #pragma unroll
    for (int mt = 0; mt < 2; mt++)
        #pragma unroll
        for (int nt = 0; nt < 8; nt++)
            #pragma unroll
            for (int i = 0; i < 4; i++) acc[mt][nt][i] = 0.f;

    auto stage = [&](int ci, int s) {
        int k0 = ci * 32;
        __half* As = smh + s * 9472;
        __half* Bs = As + 5120;
        #pragma unroll
        for (int i = 0; i < 2; i++) {
            int idx = t + i*256, row = idx >> 2, c16 = idx & 3;
            cpa16(As + row*40 + c16*8,
                  A1 + (size_t)(mloc + row)*lda + k0 + c16*8);
        }
        #pragma unroll
        for (int i = 0; i < 2; i++) {
            int idx = t + i*256, row = idx >> 4, c16 = idx & 15;
            cpa16(Bs + row*136 + c16*8,
                  W + (size_t)(k0 + row)*N + tile_n + c16*8);
        }
        cp_commit();
    };

    const int KT = K / 32;
    stage(0, 0);
    stage(1, 1);
    for (int kt = 0; kt < KT; kt++) {
        int s = kt % 3;
        cp_wait<1>();
        __syncthreads();
        const __half* As = smh + s * 9472;
        const uint32_t baddr = sbase + s*18944 + 10240 + b_lane;
        #pragma unroll
        for (int kk = 0; kk < 2; kk++) {
            uint32_t a0[4], a1[4];
            #pragma unroll
            for (int mt = 0; mt < 2; mt++) {
                uint32_t* aa = mt ? a1 : a0;
                int mrow = wm + mt*16;
                aa[0] = *(const uint32_t*)(As + (mrow + r    )*40 + kk*16 + 2*c    );
                aa[1] = *(const uint32_t*)(As + (mrow + r + 8)*40 + kk*16 + 2*c    );
                aa[2] = *(const uint32_t*)(As + (mrow + r    )*40 + kk*16 + 2*c + 8);
                aa[3] = *(const uint32_t*)(As + (mrow + r + 8)*40 + kk*16 + 2*c + 8);
            }
            #pragma unroll
            for (int ntp = 0; ntp < 4; ntp++) {
                uint32_t bf[4];
                LDSM4T(bf, baddr + kk*4352 + ntp*32);
                MMA_F16(acc[0][2*ntp],   a0, bf);
                MMA_F16(acc[0][2*ntp+1], a0, bf + 2);
                MMA_F16(acc[1][2*ntp],   a1, bf);
                MMA_F16(acc[1][2*ntp+1], a1, bf + 2);
            }
        }
        if (kt + 2 < KT) stage(kt + 2, (kt + 2) % 3);
    }

    #pragma unroll
    for (int mt = 0; mt < 2; mt++) {
        #pragma unroll
        for (int i = 0; i < 2; i++) {
            int row = tile_m + wm + mt*16 + r + i*8;
            #pragma unroll
            for (int nt = 0; nt < 8; nt++) {
                int col = tile_n + wn + nt*8 + c*2;
                float v0 = (acc[mt][nt][i*2+0] + bias[col])   * scale;
                float v1 = (acc[mt][nt][i*2+1] + bias[col+1]) * scale;
                *reinterpret_cast<uint32_t*>(C + (size_t)row*N + col)
                    = packh(v0, v1);
            }
        }
    }
}

// ---------------- tf32 GEMM (dual-W k-split, stride 136) -----------------
__global__ void __launch_bounds__(256, 2) gemm_tc(
    const float* __restrict__ Alo, const float* __restrict__ Alo2,
    const float* __restrict__ Ahi, const float* __restrict__ Ahi2,
    int lda, int ksplit,
    const float* __restrict__ Wk1, const float* __restrict__ Wk2,
    const float* __restrict__ bias,
    const float* __restrict__ Rlo, const float* __restrict__ Rhi,
    float* __restrict__ C, int N, int K)
{
    extern __shared__ float smg[];

    const int tile_n = blockIdx.x * 128;
    const int tile_m = blockIdx.y * 128;
    const int t = threadIdx.x;
    const int wid = t >> 5, lane = t & 31;
    const int wm = (wid >> 1) * 32, wn = (wid & 1) * 64;
    const int r = lane >> 2, c = lane & 3;

    const bool mhi = tile_m >= 8192;
    const float* A1 = mhi ? Ahi  : Alo;
    const float* A2 = mhi ? Ahi2 : Alo2;
    const float* Rr = mhi ? Rhi  : Rlo;
    const int mloc = mhi ? tile_m - 8192 : tile_m;

    float acc[2][8][4];
    #pragma unroll
    for (int mt = 0; mt < 2; mt++)
        #pragma unroll
        for (int nt = 0; nt < 8; nt++)
            #pragma unroll
            for (int i = 0; i < 4; i++) acc[mt][nt][i] = 0.f;

    auto stage = [&](int ci, int s) {
        int k0 = ci * 32;
        const float* Asrc; const float* Wsrc; int kcol;
        if (k0 < ksplit) { Asrc = A1; Wsrc = Wk1; kcol = k0; }
        else             { Asrc = A2; Wsrc = Wk2; kcol = k0 - ksplit; }
        float* As = smg + s * 8960;
        float* Bs = As + 4608;
        #pragma unroll
        for (int i = 0; i < 4; i++) {
            int idx = t + i*256, row = idx >> 3, c4 = idx & 7;
            cpa16(As + row*36 + c4*4,
                  Asrc + (size_t)(mloc + row)*lda + kcol + c4*4);
        }
        #pragma unroll
        for (int i = 0; i < 4; i++) {
            int idx = t + i*256, row = idx >> 5, c4 = idx & 31;
            cpa16(Bs + row*136 + c4*4,
                  Wsrc + (size_t)(kcol + row)*N + tile_n + c4*4);
        }
        cp_commit();
    };

    const int KT = K / 32;
    stage(0, 0);
    stage(1, 1);
    for (int kt = 0; kt < KT; kt++) {
        int s = kt % 3;
        cp_wait<1>();
        __syncthreads();
        const uint32_t* As = (const uint32_t*)(smg + s * 8960);
        const uint32_t* Bs = As + 4608;
        #pragma unroll
        for (int kk = 0; kk < 4; kk++) {
            uint32_t a[2][4];
            #pragma unroll
            for (int mt = 0; mt < 2; mt++) {
                int mrow = wm + mt*16;
                a[mt][0] = As[(mrow + r    )*36 + kk*8 + c    ];
                a[mt][1] = As[(mrow + r + 8)*36 + kk*8 + c    ];
                a[mt][2] = As[(mrow + r    )*36 + kk*8 + c + 4];
                a[mt][3] = As[(mrow + r + 8)*36 + kk*8 + c + 4];
            }
            #pragma unroll
            for (int nt = 0; nt < 8; nt++) {
                uint32_t b[2];
                b[0] = Bs[(kk*8 + c    )*136 + wn + nt*8 + r];
                b[1] = Bs[(kk*8 + c + 4)*136 + wn + nt*8 + r];
                MMA_TF32(acc[0][nt], a[0], b);
                MMA_TF32(acc[1][nt], a[1], b);
            }
        }
        if (kt + 2 < KT) stage(kt + 2, (kt + 2) % 3);
    }

    #pragma unroll
    for (int mt = 0; mt < 2; mt++) {
        #pragma unroll
        for (int i = 0; i < 2; i++) {
            int rofs = wm + mt*16 + r + i*8;
            int row = tile_m + rofs;
            #pragma unroll
            for (int nt = 0; nt < 8; nt++) {
                int col = tile_n + wn + nt*8 + c*2;
                float v0 = acc[mt][nt][i*2+0] + bias[col];
                float v1 = acc[mt][nt][i*2+1] + bias[col+1];
                if (Rr) {
                    v0 += Rr[(size_t)(mloc + rofs)*N + col];
                    v1 += Rr[(size_t)(mloc + rofs)*N + col + 1];
                }
                *reinterpret_cast<float2*>(C + (size_t)row*N + col)
                    = make_float2(v0, v1);
            }
        }
    }
}

// ---------------- fp16 flash attention: round-12 shape, 3-stage KV -------
// 64 q-rows, 4 warps; Q fragments loaded direct from global; single sync.
// Output fp32 (feeds FFN1's fused Wo path).
__global__ void __launch_bounds__(128) attn_h(
    const __half* __restrict__ QK,
    const __half* __restrict__ Vb,
    float* __restrict__ Ob)
{
    extern __shared__ __half smb[];
    __half* Ksm = smb;                 // 3 x [64][72]
    __half* Vsm = smb + 3*4608;        // 3 x [64][72]
    const int t = threadIdx.x;
    const int wid = t >> 5, lane = t & 31;

    const int dir = blockIdx.z;
    const __half* Qg = QK + (dir ? HALF : 0);
    const __half* Kg = QK + (dir ? 0 : HALF);
    const __half* Vg = Vb + (dir ? 0 : HALF);
    float* Og = Ob + (dir ? HALF : 0);

    const int bh = blockIdx.y;
    const int b = bh >> 2, h = bh & 3;
    const int hoff = h * DHd;
    const int qbase = b * Nn + blockIdx.x * 64;
    const int r = lane >> 2, c = lane & 3;
    const int qr0 = wid * 16;

    auto stageKV = [&](int kt, int s) {
        int kbase = b * Nn + kt * 64;
        #pragma unroll
        for (int i = 0; i < 4; i++) {
            int idx = t + i*128, row = idx >> 3, c8 = idx & 7;
            cpa16(Ksm + s*4608 + row*72 + c8*8,
                  Kg + (size_t)(kbase + row)*Dd + hoff + c8*8);
            cpa16(Vsm + s*4608 + row*72 + c8*8,
                  Vg + (size_t)(kbase + row)*Dd + hoff + c8*8);
        }
        cp_commit();
    };
    stageKV(0, 0);
    stageKV(1, 1);

    // Q fragments direct from global (one-time)
    uint32_t qa[4][4];
    {
        const __half* q0 = Qg + (size_t)(qbase + qr0 + r    )*Dd + hoff;
        const __half* q1 = Qg + (size_t)(qbase + qr0 + r + 8)*Dd + hoff;
        #pragma unroll
        for (int kk = 0; kk < 4; kk++) {
            qa[kk][0] = *(const uint32_t*)(q0 + kk*16 + 2*c    );
            qa[kk][1] = *(const uint32_t*)(q1 + kk*16 + 2*c    );
            qa[kk][2] = *(const uint32_t*)(q0 + kk*16 + 2*c + 8);
            qa[kk][3] = *(const uint32_t*)(q1 + kk*16 + 2*c + 8);
        }
    }

    const int kl4 = ((lane & 7) + ((lane >> 4) & 1)*8)*72 + ((lane >> 3) & 1)*8;
    const int vl4 = (lane & 15)*72 + ((lane >> 4) & 1)*8;

    float o[8][4];
    #pragma unroll
    for (int nt = 0; nt < 8; nt++)
        #pragma unroll
        for (int i = 0; i < 4; i++) o[nt][i] = 0.f;
    float l0 = 0.f, l1 = 0.f;

    for (int kt = 0; kt < Nn/64; kt++) {
        int s = kt % 3;
        cp_wait<1>();
        __syncthreads();
        const uint32_t ksb = su32(Ksm + s*4608) + kl4*2;
        const uint32_t vsb = su32(Vsm + s*4608) + vl4*2;

        float sc[8][4];
        #pragma unroll
        for (int nt = 0; nt < 8; nt++)
            #pragma unroll
            for (int i = 0; i < 4; i++) sc[nt][i] = 0.f;
        #pragma unroll
        for (int kk = 0; kk < 4; kk++) {
            #pragma unroll
            for (int ntp = 0; ntp < 4; ntp++) {
                uint32_t bfr[4];
                LDSM4(bfr, ksb + (ntp*16*72 + kk*16)*2);
                MMA_F16(sc[2*ntp],   qa[kk], bfr);
                MMA_F16(sc[2*ntp+1], qa[kk], bfr + 2);
            }
        }

        uint32_t pf[8][2];
        #pragma unroll
        for (int nt = 0; nt < 8; nt++) {
            float p0 = __expf(sc[nt][0]);
            float p1 = __expf(sc[nt][1]);
            float p2 = __expf(sc[nt][2]);
            float p3 = __expf(sc[nt][3]);
            l0 += p0 + p1;
            l1 += p2 + p3;
            pf[nt][0] = packh(p0, p1);
            pf[nt][1] = packh(p2, p3);
        }

        #pragma unroll
        for (int kk = 0; kk < 4; kk++) {
            uint32_t a[4] = { pf[2*kk][0], pf[2*kk][1],
                              pf[2*kk+1][0], pf[2*kk+1][1] };
            #pragma unroll
            for (int ntp = 0; ntp < 4; ntp++) {
                uint32_t bfr[4];
                LDSM4T(bfr, vsb + (kk*16*72 + ntp*16)*2);
                MMA_F16(o[2*ntp],   a, bfr);
                MMA_F16(o[2*ntp+1], a, bfr + 2);
            }
        }

        if (kt + 2 < Nn/64) stageKV(kt + 2, (kt + 2) % 3);
    }

    l0 += __shfl_xor_sync(0xffffffffu, l0, 1);
    l0 += __shfl_xor_sync(0xffffffffu, l0, 2);
    l1 += __shfl_xor_sync(0xffffffffu, l1, 1);
    l1 += __shfl_xor_sync(0xffffffffu, l1, 2);
    float inv0 = 1.f / l0, inv1 = 1.f / l1;

    int row0 = qbase + qr0 + r, row1 = row0 + 8;
    #pragma unroll
    for (int nt = 0; nt < 8; nt++) {
        int col = hoff + nt*8 + c*2;
        *reinterpret_cast<float2*>(Og + (size_t)row0*Dd + col)
            = make_float2(o[nt][0]*inv0, o[nt][1]*inv0);
        *reinterpret_cast<float2*>(Og + (size_t)row1*Dd + col)
            = make_float2(o[nt][2]*inv1, o[nt][3]*inv1);
    }
}

// ---------------- LayerNorm + exact GELU (fp32 -> fp32) ------------------
__global__ void __launch_bounds__(128) lngelu_kernel(
    const float* __restrict__ Hsrc,
    const float* __restrict__ g,
    const float* __restrict__ bb,
    float* __restrict__ out)
{
    __shared__ float red[8];
    const int rrow = blockIdx.x;
    const int t = threadIdx.x;
    const int lane = t & 31, wid = t >> 5;
    float4 x = *reinterpret_cast<const float4*>(Hsrc + (size_t)rrow*512 + t*4);

    float sum = x.x + x.y + x.z + x.w;
    #pragma unroll
    for (int off = 16; off; off >>= 1)
        sum += __shfl_xor_sync(0xffffffffu, sum, off);
    if (lane == 0) red[wid] = sum;
    __syncthreads();
    sum = red[lane & 3];
    sum += __shfl_xor_sync(0xffffffffu, sum, 1);
    sum += __shfl_xor_sync(0xffffffffu, sum, 2);
    float mu = sum * (1.0f/512.0f);

    float4 d = make_float4(x.x-mu, x.y-mu, x.z-mu, x.w-mu);
    float vs = d.x*d.x + d.y*d.y + d.z*d.z + d.w*d.w;
    #pragma unroll
    for (int off = 16; off; off >>= 1)
        vs += __shfl_xor_sync(0xffffffffu, vs, off);
    __syncthreads();
    if (lane == 0) red[4 + wid] = vs;
    __syncthreads();
    vs = red[4 + (lane & 3)];
    vs += __shfl_xor_sync(0xffffffffu, vs, 1);
    vs += __shfl_xor_sync(0xffffffffu, vs, 2);
    float rstd = rsqrtf(vs * (1.0f/512.0f) + 1e-5f);

    float4 gg = *reinterpret_cast<const float4*>(g  + t*4);
    float4 bv = *reinterpret_cast<const float4*>(bb + t*4);
    float y0 = d.x * rstd * gg.x + bv.x;
    float y1 = d.y * rstd * gg.y + bv.y;
    float y2 = d.z * rstd * gg.z + bv.z;
    float y3 = d.w * rstd * gg.w + bv.w;
    const float RS2 = 0.70710678118654752f;
    float4 o4;
    o4.x = 0.5f*y0*(1.0f + erff(y0*RS2));
    o4.y = 0.5f*y1*(1.0f + erff(y1*RS2));
    o4.z = 0.5f*y2*(1.0f + erff(y2*RS2));
    o4.w = 0.5f*y3*(1.0f + erff(y3*RS2));
    *reinterpret_cast<float4*>(out + (size_t)rrow*512 + t*4) = o4;
}

// ---------------- launcher ----------------
extern "C" void kernel_launch(void* const* d_in, const int* in_sizes, int n_in,
                              void* d_out, int out_size)
{
    const float* x0  = (const float*)d_in[0];
    const float* x1  = (const float*)d_in[1];
    const float* Wqk = (const float*)d_in[2];
    const float* bqk = (const float*)d_in[3];
    const float* Wv  = (const float*)d_in[4];
    const float* bv  = (const float*)d_in[5];
    const float* Wo  = (const float*)d_in[6];
    const float* bo  = (const float*)d_in[7];
    const float* W1  = (const float*)d_in[8];
    const float* b1  = (const float*)d_in[9];
    const float* lng = (const float*)d_in[10];
    const float* lnb = (const float*)d_in[11];
    const float* W2  = (const float*)d_in[12];
    const float* b2  = (const float*)d_in[13];
    float* out = (float*)d_out;

    __half *xh, *qkh, *vh, *wh;
    float *m, *hbuf, *a, *wf, *b1p, *zerov;
    cudaGetSymbolAddress((void**)&xh,   g_xh);
    cudaGetSymbolAddress((void**)&qkh,  g_qkh);
    cudaGetSymbolAddress((void**)&vh,   g_vh);
    cudaGetSymbolAddress((void**)&m,    g_m);
    cudaGetSymbolAddress((void**)&hbuf, g_h);
    cudaGetSymbolAddress((void**)&a,    g_a);
    cudaGetSymbolAddress((void**)&wh,   g_wh);
    cudaGetSymbolAddress((void**)&wf,   g_wf);
    cudaGetSymbolAddress((void**)&b1p,  g_b1p);
    cudaGetSymbolAddress((void**)&zerov,g_zero);

    __half* Wqk_h = wh;
    __half* Wv_h  = wh + 65536;

    const float SS = 0.35355339059327373f;   // 64^-0.25
    const int GSH = 3 * 18944;
    const int GST = 3 * 8960 * 4;
    const int AS = 6 * 4608 * 2;              // 55296 B
    cudaFuncSetAttribute(gemm_hc,
        cudaFuncAttributeMaxDynamicSharedMemorySize, GSH);
    cudaFuncSetAttribute(gemm_tc,
        cudaFuncAttributeMaxDynamicSharedMemorySize, GST);
    cudaFuncSetAttribute(attn_h,
        cudaFuncAttributeMaxDynamicSharedMemorySize, AS);

    // conversions (x pair + Wqk + Wv)
    cvt_all<<<(2*HALF + 2*65536)/1024, 256>>>(x0, x1, Wqk, Wv, xh, wh);

    const int BIG = 1 << 20;
    // Wfused = Wo @ W1_bot  (256x512, K=256)
    gemm_tc<<<dim3(4,2), 256, GST>>>(
        Wo, Wo, Wo, Wo, 256, BIG,
        W1 + 256*512, W1 + 256*512, zerov, nullptr, nullptr, wf, 512, 256);
    // b1p = b1 + bo @ W1_bot
    biasfold<<<2, 256>>>(b1, bo, W1, b1p);

    // fused qk & v projections (fp16), z=0: qk*SS, z=1: v
    gemm_hc<<<dim3(2,128,2), 256, GSH>>>(
        xh, xh + HALF, 256,
        Wqk_h, bqk, qkh, SS, Wv_h, bv, vh, 1.f, 256, 256);

    // bidirectional flash attention -> m (fp32)
    attn_h<<<dim3(32,16,2), dim3(128), AS>>>(qkh, vh, m);

    // FFN GEMM1 (tf32): x@W1_top + m@Wfused + b1p -> h
    gemm_tc<<<dim3(4,128), 256, GST>>>(
        x0, m, x1, m + HALF, 256, 256,
        W1, wf, b1p, nullptr, nullptr, hbuf, 512, 512);

    // LayerNorm + exact GELU (fp32)
    lngelu_kernel<<<16384, 128>>>(hbuf, lng, lnb, a);

    // FFN GEMM2 (tf32) + residual
    gemm_tc<<<dim3(2,128), 256, GST>>>(
        a, a, a + HHALF, a + HHALF, 512, BIG,
        W2, W2, b2, x0, x1, out, 256, 512);
}

// round 17
// speedup vs baseline: 1.0582x; 1.0582x over previous
#include <cuda_runtime.h>
#include <cuda_fp16.h>
#include <math.h>
#include <stdint.h>

#define Nn   2048
#define Dd   256
#define DHd  64
#define ROWS 8192
#define HALF  (ROWS*Dd)
#define HHALF (ROWS*512)

// ---------------- scratch ----------------
__device__ __half g_xh [2*ROWS*Dd];
__device__ __half g_qkh[2*ROWS*Dd];
__device__ __half g_vh [2*ROWS*Dd];
__device__ __half g_mh [2*ROWS*Dd];
__device__ float  g_mo [2*ROWS*Dd];
__device__ float  g_h  [2*ROWS*512];
__device__ float  g_a  [2*ROWS*512];
__device__ __half g_wh [3*65536];

// ---------------- helpers ----------------
__device__ __forceinline__ uint32_t packh(float lo, float hi) {
    __half2 h = __floats2half2_rn(lo, hi);
    return *reinterpret_cast<uint32_t*>(&h);
}
__device__ __forceinline__ uint32_t su32(const void* p) {
    return (uint32_t)__cvta_generic_to_shared(p);
}
__device__ __forceinline__ void cpa16(void* dst, const void* src) {
    asm volatile("cp.async.cg.shared.global [%0], [%1], 16;"
                 :: "r"(su32(dst)), "l"(src));
}
__device__ __forceinline__ void cp_commit() {
    asm volatile("cp.async.commit_group;");
}
template <int N> __device__ __forceinline__ void cp_wait() {
    asm volatile("cp.async.wait_group %0;" :: "n"(N));
}

#define LDSM4(r, addr) \
    asm volatile("ldmatrix.sync.aligned.m8n8.x4.shared.b16 {%0,%1,%2,%3}, [%4];" \
                 : "=r"((r)[0]), "=r"((r)[1]), "=r"((r)[2]), "=r"((r)[3]) \
                 : "r"(addr))
#define LDSM4T(r, addr) \
    asm volatile("ldmatrix.sync.aligned.m8n8.x4.trans.shared.b16 {%0,%1,%2,%3}, [%4];" \
                 : "=r"((r)[0]), "=r"((r)[1]), "=r"((r)[2]), "=r"((r)[3]) \
                 : "r"(addr))

#define MMA_F16(c, a, b) \
    asm volatile("mma.sync.aligned.m16n8k16.row.col.f32.f16.f16.f32 " \
                 "{%0,%1,%2,%3},{%4,%5,%6,%7},{%8,%9},{%0,%1,%2,%3};" \
                 : "+f"((c)[0]), "+f"((c)[1]), "+f"((c)[2]), "+f"((c)[3]) \
                 : "r"((a)[0]), "r"((a)[1]), "r"((a)[2]), "r"((a)[3]), \
                   "r"((b)[0]), "r"((b)[1]))

#define MMA_TF32(c, a, b) \
    asm volatile("mma.sync.aligned.m16n8k8.row.col.f32.tf32.tf32.f32 " \
                 "{%0,%1,%2,%3},{%4,%5,%6,%7},{%8,%9},{%0,%1,%2,%3};" \
                 : "+f"((c)[0]), "+f"((c)[1]), "+f"((c)[2]), "+f"((c)[3]) \
                 : "r"((a)[0]), "r"((a)[1]), "r"((a)[2]), "r"((a)[3]), \
                   "r"((b)[0]), "r"((b)[1]))

// ---------------- fused fp32 -> fp16 conversion (x pair + 3 weights) -----
__global__ void __launch_bounds__(256) cvt_all(
    const float* __restrict__ x0, const float* __restrict__ x1,
    const float* __restrict__ w0, const float* __restrict__ w1,
    const float* __restrict__ w2,
    __half* __restrict__ xdst, __half* __restrict__ wdst)
{
    int i = (blockIdx.x * 256 + threadIdx.x) * 4;
    const float* src;
    __half* dst;
    int j;
    if (i < HALF)           { src = x0; j = i;        dst = xdst + i; }
    else if (i < 2*HALF)    { src = x1; j = i - HALF; dst = xdst + i; }
    else {
        int k = i - 2*HALF;
        dst = wdst + k;
        if (k < 65536)       { src = w0; j = k; }
        else if (k < 131072) { src = w1; j = k - 65536; }
        else                 { src = w2; j = k - 131072; }
    }
    float4 v = *reinterpret_cast<const float4*>(src + j);
    uint2 u;
    u.x = packh(v.x, v.y);
    u.y = packh(v.z, v.w);
    *reinterpret_cast<uint2*>(dst) = u;
}

// ---------------- fp16 GEMM (validated round-10/11/12 structure) ---------
template <typename OutT>
__global__ void __launch_bounds__(256, 2) gemm_hc(
    const __half* __restrict__ Alo, const __half* __restrict__ Ahi, int lda,
    const __half* __restrict__ Wa, const float* __restrict__ biasa,
    OutT* __restrict__ Ca, float scalea,
    const __half* __restrict__ Wb, const float* __restrict__ biasb,
    OutT* __restrict__ Cb, float scaleb,
    int N, int K)
{
    extern __shared__ __half smh[];

    const __half* W   = blockIdx.z ? Wb : Wa;
    const float* bias = blockIdx.z ? biasb : biasa;
    OutT* C           = blockIdx.z ? Cb : Ca;
    const float scale = blockIdx.z ? scaleb : scalea;

    const int tile_n = blockIdx.x * 128;
    const int tile_m = blockIdx.y * 128;
    const int t = threadIdx.x;
    const int wid = t >> 5, lane = t & 31;
    const int wm = (wid >> 1) * 32, wn = (wid & 1) * 64;
    const int r = lane >> 2, c = lane & 3;

    const bool mhi = tile_m >= 8192;
    const __half* A1 = mhi ? Ahi : Alo;
    const int mloc = mhi ? tile_m - 8192 : tile_m;

    const uint32_t sbase = su32(smh);
    const int b_lane = ((lane & 15)*136 + ((lane >> 4) & 1)*8 + wn) * 2;

    float acc[2][8][4];
    #pragma unroll
    for (int mt = 0; mt < 2; mt++)
        #pragma unroll
        for (int nt = 0; nt < 8; nt++)
            #pragma unroll
            for (int i = 0; i < 4; i++) acc[mt][nt][i] = 0.f;

    auto stage = [&](int ci, int s) {
        int k0 = ci * 32;
        __half* As = smh + s * 9472;
        __half* Bs = As + 5120;
        #pragma unroll
        for (int i = 0; i < 2; i++) {
            int idx = t + i*256, row = idx >> 2, c16 = idx & 3;
            cpa16(As + row*40 + c16*8,
                  A1 + (size_t)(mloc + row)*lda + k0 + c16*8);
        }
        #pragma unroll
        for (int i = 0; i < 2; i++) {
            int idx = t + i*256, row = idx >> 4, c16 = idx & 15;
            cpa16(Bs + row*136 + c16*8,
                  W + (size_t)(k0 + row)*N + tile_n + c16*8);
        }
        cp_commit();
    };

    const int KT = K / 32;
    stage(0, 0);
    stage(1, 1);
    for (int kt = 0; kt < KT; kt++) {
        int s = kt % 3;
        cp_wait<1>();
        __syncthreads();
        const __half* As = smh + s * 9472;
        const uint32_t baddr = sbase + s*18944 + 10240 + b_lane;
        #pragma unroll
        for (int kk = 0; kk < 2; kk++) {
            uint32_t a0[4], a1[4];
            #pragma unroll
            for (int mt = 0; mt < 2; mt++) {
                uint32_t* aa = mt ? a1 : a0;
                int mrow = wm + mt*16;
                aa[0] = *(const uint32_t*)(As + (mrow + r    )*40 + kk*16 + 2*c    );
                aa[1] = *(const uint32_t*)(As + (mrow + r + 8)*40 + kk*16 + 2*c    );
                aa[2] = *(const uint32_t*)(As + (mrow + r    )*40 + kk*16 + 2*c + 8);
                aa[3] = *(const uint32_t*)(As + (mrow + r + 8)*40 + kk*16 + 2*c + 8);
            }
            #pragma unroll
            for (int ntp = 0; ntp < 4; ntp++) {
                uint32_t bf[4];
                LDSM4T(bf, baddr + kk*4352 + ntp*32);
                MMA_F16(acc[0][2*ntp],   a0, bf);
                MMA_F16(acc[0][2*ntp+1], a0, bf + 2);
                MMA_F16(acc[1][2*ntp],   a1, bf);
                MMA_F16(acc[1][2*ntp+1], a1, bf + 2);
            }
        }
        if (kt + 2 < KT) stage(kt + 2, (kt + 2) % 3);
    }

    #pragma unroll
    for (int mt = 0; mt < 2; mt++) {
        #pragma unroll
        for (int i = 0; i < 2; i++) {
            int row = tile_m + wm + mt*16 + r + i*8;
            #pragma unroll
            for (int nt = 0; nt < 8; nt++) {
                int col = tile_n + wn + nt*8 + c*2;
                float v0 = (acc[mt][nt][i*2+0] + bias[col])   * scale;
                float v1 = (acc[mt][nt][i*2+1] + bias[col+1]) * scale;
                if constexpr (sizeof(OutT) == 2) {
                    *reinterpret_cast<uint32_t*>(
                        (__half*)C + (size_t)row*N + col) = packh(v0, v1);
                } else {
                    *reinterpret_cast<float2*>(
                        (float*)C + (size_t)row*N + col) = make_float2(v0, v1);
                }
            }
        }
    }
}

// ---------------- tf32 GEMM for the FFN (validated, stride 136) ----------
__global__ void __launch_bounds__(256, 2) gemm_tc(
    const float* __restrict__ Alo, const float* __restrict__ Alo2,
    const float* __restrict__ Ahi, const float* __restrict__ Ahi2,
    int lda, int ksplit,
    const float* __restrict__ W, const float* __restrict__ bias,
    const float* __restrict__ Rlo, const float* __restrict__ Rhi,
    float* __restrict__ C, int N, int K)
{
    extern __shared__ float smg[];

    const int tile_n = blockIdx.x * 128;
    const int tile_m = blockIdx.y * 128;
    const int t = threadIdx.x;
    const int wid = t >> 5, lane = t & 31;
    const int wm = (wid >> 1) * 32, wn = (wid & 1) * 64;
    const int r = lane >> 2, c = lane & 3;

    const bool mhi = tile_m >= 8192;
    const float* A1 = mhi ? Ahi  : Alo;
    const float* A2 = mhi ? Ahi2 : Alo2;
    const float* Rr = mhi ? Rhi  : Rlo;
    const int mloc = mhi ? tile_m - 8192 : tile_m;

    float acc[2][8][4];
    #pragma unroll
    for (int mt = 0; mt < 2; mt++)
        #pragma unroll
        for (int nt = 0; nt < 8; nt++)
            #pragma unroll
            for (int i = 0; i < 4; i++) acc[mt][nt][i] = 0.f;

    auto stage = [&](int ci, int s) {
        int k0 = ci * 32;
        const float* Asrc; int kcol;
        if (k0 < ksplit) { Asrc = A1; kcol = k0; }
        else             { Asrc = A2; kcol = k0 - ksplit; }
        float* As = smg + s * 8960;
        float* Bs = As + 4608;
        #pragma unroll
        for (int i = 0; i < 4; i++) {
            int idx = t + i*256, row = idx >> 3, c4 = idx & 7;
            cpa16(As + row*36 + c4*4,
                  Asrc + (size_t)(mloc + row)*lda + kcol + c4*4);
        }
        #pragma unroll
        for (int i = 0; i < 4; i++) {
            int idx = t + i*256, row = idx >> 5, c4 = idx & 31;
            cpa16(Bs + row*136 + c4*4,
                  W + (size_t)(k0 + row)*N + tile_n + c4*4);
        }
        cp_commit();
    };

    const int KT = K / 32;
    stage(0, 0);
    stage(1, 1);
    for (int kt = 0; kt < KT; kt++) {
        int s = kt % 3;
        cp_wait<1>();
        __syncthreads();
        const uint32_t* As = (const uint32_t*)(smg + s * 8960);
        const uint32_t* Bs = As + 4608;
        #pragma unroll
        for (int kk = 0; kk < 4; kk++) {
            uint32_t a[2][4];
            #pragma unroll
            for (int mt = 0; mt < 2; mt++) {
                int mrow = wm + mt*16;
                a[mt][0] = As[(mrow + r    )*36 + kk*8 + c    ];
                a[mt][1] = As[(mrow + r + 8)*36 + kk*8 + c    ];
                a[mt][2] = As[(mrow + r    )*36 + kk*8 + c + 4];
                a[mt][3] = As[(mrow + r + 8)*36 + kk*8 + c + 4];
            }
            #pragma unroll
            for (int nt = 0; nt < 8; nt++) {
                uint32_t b[2];
                b[0] = Bs[(kk*8 + c    )*136 + wn + nt*8 + r];
                b[1] = Bs[(kk*8 + c + 4)*136 + wn + nt*8 + r];
                MMA_TF32(acc[0][nt], a[0], b);
                MMA_TF32(acc[1][nt], a[1], b);
            }
        }
        if (kt + 2 < KT) stage(kt + 2, (kt + 2) % 3);
    }

    #pragma unroll
    for (int mt = 0; mt < 2; mt++) {
        #pragma unroll
        for (int i = 0; i < 2; i++) {
            int rofs = wm + mt*16 + r + i*8;
            int row = tile_m + rofs;
            #pragma unroll
            for (int nt = 0; nt < 8; nt++) {
                int col = tile_n + wn + nt*8 + c*2;
                float v0 = acc[mt][nt][i*2+0] + bias[col];
                float v1 = acc[mt][nt][i*2+1] + bias[col+1];
                if (Rr) {
                    v0 += Rr[(size_t)(mloc + rofs)*N + col];
                    v1 += Rr[(size_t)(mloc + rofs)*N + col + 1];
                }
                *reinterpret_cast<float2*>(C + (size_t)row*N + col)
                    = make_float2(v0, v1);
            }
        }
    }
}

// ---------------- fp16 flash attention (round-12 exact) ------------------
__global__ void __launch_bounds__(128) attn_h(
    const __half* __restrict__ QK,
    const __half* __restrict__ Vb,
    __half* __restrict__ Ob)
{
    extern __shared__ __half smb[];
    __half* Qs  = smb;
    __half* Ksm = smb + 4608;
    __half* Vsm = smb + 3*4608;
    const int t = threadIdx.x;
    const int wid = t >> 5, lane = t & 31;

    const int dir = blockIdx.z;
    const __half* Qg = QK + (dir ? HALF : 0);
    const __half* Kg = QK + (dir ? 0 : HALF);
    const __half* Vg = Vb + (dir ? 0 : HALF);
    __half* Og = Ob + (dir ? HALF : 0);

    const int bh = blockIdx.y;
    const int b = bh >> 2, h = bh & 3;
    const int hoff = h * DHd;
    const int qbase = b * Nn + blockIdx.x * 64;
    const int r = lane >> 2, c = lane & 3;
    const int qr0 = wid * 16;

    #pragma unroll
    for (int i = 0; i < 4; i++) {
        int idx = t + i*128, row = idx >> 3, c8 = idx & 7;
        cpa16(Qs + row*72 + c8*8,
              Qg + (size_t)(qbase + row)*Dd + hoff + c8*8);
    }
    auto stageKV = [&](int kt, int s) {
        int kbase = b * Nn + kt * 64;
        #pragma unroll
        for (int i = 0; i < 4; i++) {
            int idx = t + i*128, row = idx >> 3, c8 = idx & 7;
            cpa16(Ksm + s*4608 + row*72 + c8*8,
                  Kg + (size_t)(kbase + row)*Dd + hoff + c8*8);
            cpa16(Vsm + s*4608 + row*72 + c8*8,
                  Vg + (size_t)(kbase + row)*Dd + hoff + c8*8);
        }
        cp_commit();
    };
    stageKV(0, 0);

    const int kl4 = ((lane & 7) + ((lane >> 4) & 1)*8)*72 + ((lane >> 3) & 1)*8;
    const int vl4 = (lane & 15)*72 + ((lane >> 4) & 1)*8;

    uint32_t qa[4][4];
    float o[8][4];
    #pragma unroll
    for (int nt = 0; nt < 8; nt++)
        #pragma unroll
        for (int i = 0; i < 4; i++) o[nt][i] = 0.f;
    float l0 = 0.f, l1 = 0.f;

    for (int kt = 0; kt < Nn/64; kt++) {
        int s = kt & 1;
        if (kt + 1 < Nn/64) { stageKV(kt+1, s ^ 1); cp_wait<1>(); }
        else                { cp_wait<0>(); }
        __syncthreads();

        if (kt == 0) {
            #pragma unroll
            for (int kk = 0; kk < 4; kk++) {
                qa[kk][0] = *(const uint32_t*)(Qs + (qr0+r  )*72 + kk*16 + 2*c    );
                qa[kk][1] = *(const uint32_t*)(Qs + (qr0+r+8)*72 + kk*16 + 2*c    );
                qa[kk][2] = *(const uint32_t*)(Qs + (qr0+r  )*72 + kk*16 + 2*c + 8);
                qa[kk][3] = *(const uint32_t*)(Qs + (qr0+r+8)*72 + kk*16 + 2*c + 8);
            }
        }
        const uint32_t ksb = su32(Ksm + s*4608) + kl4*2;
        const uint32_t vsb = su32(Vsm + s*4608) + vl4*2;

        float sc[8][4];
        #pragma unroll
        for (int nt = 0; nt < 8; nt++)
            #pragma unroll
            for (int i = 0; i < 4; i++) sc[nt][i] = 0.f;
        #pragma unroll
        for (int kk = 0; kk < 4; kk++) {
            #pragma unroll
            for (int ntp = 0; ntp < 4; ntp++) {
                uint32_t bfr[4];
                LDSM4(bfr, ksb + (ntp*16*72 + kk*16)*2);
                MMA_F16(sc[2*ntp],   qa[kk], bfr);
                MMA_F16(sc[2*ntp+1], qa[kk], bfr + 2);
            }
        }

        uint32_t pf[8][2];
        #pragma unroll
        for (int nt = 0; nt < 8; nt++) {
            float p0 = __expf(sc[nt][0]);
            float p1 = __expf(sc[nt][1]);
            float p2 = __expf(sc[nt][2]);
            float p3 = __expf(sc[nt][3]);
            l0 += p0 + p1;
            l1 += p2 + p3;
            pf[nt][0] = packh(p0, p1);
            pf[nt][1] = packh(p2, p3);
        }

        #pragma unroll
        for (int kk = 0; kk < 4; kk++) {
            uint32_t a[4] = { pf[2*kk][0], pf[2*kk][1],
                              pf[2*kk+1][0], pf[2*kk+1][1] };
            #pragma unroll
            for (int ntp = 0; ntp < 4; ntp++) {
                uint32_t bfr[4];
                LDSM4T(bfr, vsb + (kk*16*72 + ntp*16)*2);
                MMA_F16(o[2*ntp],   a, bfr);
                MMA_F16(o[2*ntp+1], a, bfr + 2);
            }
        }
        __syncthreads();
    }

    l0 += __shfl_xor_sync(0xffffffffu, l0, 1);
    l0 += __shfl_xor_sync(0xffffffffu, l0, 2);
    l1 += __shfl_xor_sync(0xffffffffu, l1, 1);
    l1 += __shfl_xor_sync(0xffffffffu, l1, 2);
    float inv0 = 1.f / l0, inv1 = 1.f / l1;

    int row0 = qbase + qr0 + r, row1 = row0 + 8;
    #pragma unroll
    for (int nt = 0; nt < 8; nt++) {
        int col = hoff + nt*8 + c*2;
        *reinterpret_cast<uint32_t*>(Og + (size_t)row0*Dd + col)
            = packh(o[nt][0]*inv0, o[nt][1]*inv0);
        *reinterpret_cast<uint32_t*>(Og + (size_t)row1*Dd + col)
            = packh(o[nt][2]*inv1, o[nt][3]*inv1);
    }
}

// ---------------- LayerNorm + exact GELU (fp32 -> fp32) ------------------
__global__ void __launch_bounds__(128) lngelu_kernel(
    const float* __restrict__ Hsrc,
    const float* __restrict__ g,
    const float* __restrict__ bb,
    float* __restrict__ out)
{
    __shared__ float red[8];
    const int rrow = blockIdx.x;
    const int t = threadIdx.x;
    const int lane = t & 31, wid = t >> 5;
    float4 x = *reinterpret_cast<const float4*>(Hsrc + (size_t)rrow*512 + t*4);

    float sum = x.x + x.y + x.z + x.w;
    #pragma unroll
    for (int off = 16; off; off >>= 1)
        sum += __shfl_xor_sync(0xffffffffu, sum, off);
    if (lane == 0) red[wid] = sum;
    __syncthreads();
    sum = red[lane & 3];
    sum += __shfl_xor_sync(0xffffffffu, sum, 1);
    sum += __shfl_xor_sync(0xffffffffu, sum, 2);
    float mu = sum * (1.0f/512.0f);

    float4 d = make_float4(x.x-mu, x.y-mu, x.z-mu, x.w-mu);
    float vs = d.x*d.x + d.y*d.y + d.z*d.z + d.w*d.w;
    #pragma unroll
    for (int off = 16; off; off >>= 1)
        vs += __shfl_xor_sync(0xffffffffu, vs, off);
    __syncthreads();
    if (lane == 0) red[4 + wid] = vs;
    __syncthreads();
    vs = red[4 + (lane & 3)];
    vs += __shfl_xor_sync(0xffffffffu, vs, 1);
    vs += __shfl_xor_sync(0xffffffffu, vs, 2);
    float rstd = rsqrtf(vs * (1.0f/512.0f) + 1e-5f);

    float4 gg = *reinterpret_cast<const float4*>(g  + t*4);
    float4 bv = *reinterpret_cast<const float4*>(bb + t*4);
    float y0 = d.x * rstd * gg.x + bv.x;
    float y1 = d.y * rstd * gg.y + bv.y;
    float y2 = d.z * rstd * gg.z + bv.z;
    float y3 = d.w * rstd * gg.w + bv.w;
    const float RS2 = 0.70710678118654752f;
    float4 o4;
    o4.x = 0.5f*y0*(1.0f + erff(y0*RS2));
    o4.y = 0.5f*y1*(1.0f + erff(y1*RS2));
    o4.z = 0.5f*y2*(1.0f + erff(y2*RS2));
    o4.w = 0.5f*y3*(1.0f + erff(y3*RS2));
    *reinterpret_cast<float4*>(out + (size_t)rrow*512 + t*4) = o4;
}

// ---------------- launcher ----------------
extern "C" void kernel_launch(void* const* d_in, const int* in_sizes, int n_in,
                              void* d_out, int out_size)
{
    const float* x0  = (const float*)d_in[0];
    const float* x1  = (const float*)d_in[1];
    const float* Wqk = (const float*)d_in[2];
    const float* bqk = (const float*)d_in[3];
    const float* Wv  = (const float*)d_in[4];
    const float* bv  = (const float*)d_in[5];
    const float* Wo  = (const float*)d_in[6];
    const float* bo  = (const float*)d_in[7];
    const float* W1  = (const float*)d_in[8];
    const float* b1  = (const float*)d_in[9];
    const float* lng = (const float*)d_in[10];
    const float* lnb = (const float*)d_in[11];
    const float* W2  = (const float*)d_in[12];
    const float* b2  = (const float*)d_in[13];
    float* out = (float*)d_out;

    __half *xh, *qkh, *vh, *mh, *wh;
    float *mo, *hbuf, *a;
    cudaGetSymbolAddress((void**)&xh,   g_xh);
    cudaGetSymbolAddress((void**)&qkh,  g_qkh);
    cudaGetSymbolAddress((void**)&vh,   g_vh);
    cudaGetSymbolAddress((void**)&mh,   g_mh);
    cudaGetSymbolAddress((void**)&mo,   g_mo);
    cudaGetSymbolAddress((void**)&hbuf, g_h);
    cudaGetSymbolAddress((void**)&a,    g_a);
    cudaGetSymbolAddress((void**)&wh,   g_wh);

    __half* Wqk_h = wh;
    __half* Wv_h  = wh + 65536;
    __half* Wo_h  = wh + 131072;

    const float SS = 0.35355339059327373f;   // 64^-0.25
    const int GSH = 3 * 18944;               // fp16 gemm smem
    const int GST = 3 * 8960 * 4;            // tf32 gemm smem
    const int AS = 5 * 4608 * 2;             // attention smem
    cudaFuncSetAttribute(gemm_hc<float>,
        cudaFuncAttributeMaxDynamicSharedMemorySize, GSH);
    cudaFuncSetAttribute(gemm_hc<__half>,
        cudaFuncAttributeMaxDynamicSharedMemorySize, GSH);
    cudaFuncSetAttribute(gemm_tc,
        cudaFuncAttributeMaxDynamicSharedMemorySize, GST);
    cudaFuncSetAttribute(attn_h,
        cudaFuncAttributeMaxDynamicSharedMemorySize, AS);

    // fused conversions: x pair + Wqk + Wv + Wo (single launch)
    cvt_all<<<(2*HALF + 3*65536)/1024, 256>>>(x0, x1, Wqk, Wv, Wo, xh, wh);

    // fused qk & v projections (fp16), z=0: qk*SS, z=1: v
    gemm_hc<__half><<<dim3(2,128,2), 256, GSH>>>(
        xh, xh + HALF, 256,
        Wqk_h, bqk, qkh, SS, Wv_h, bv, vh, 1.f, 256, 256);

    // bidirectional flash attention (fp16) -> mh
    attn_h<<<dim3(32,16,2), dim3(128), AS>>>(qkh, vh, mh);

    // output projection (fp16 GEMM, fp32 out)
    gemm_hc<float><<<dim3(2,128), 256, GSH>>>(
        mh, mh + HALF, 256,
        Wo_h, bo, mo, 1.f, nullptr, nullptr, nullptr, 0.f, 256, 256);

    // FFN GEMM1 (tf32): concat_K([x, mo]) @ W1 + b1 -> fp32 h
    const int BIG = 1 << 20;
    gemm_tc<<<dim3(4,128), 256, GST>>>(
        x0, mo, x1, mo + HALF, 256, 256,
        W1, b1, nullptr, nullptr, hbuf, 512, 512);

    // LayerNorm + exact GELU (fp32)
    lngelu_kernel<<<16384, 128>>>(hbuf, lng, lnb, a);

    // FFN GEMM2 (tf32) + residual
    gemm_tc<<<dim3(2,128), 256, GST>>>(
        a, a, a + HHALF, a + HHALF, 512, BIG,
        W2, b2, x0, x1, out, 256, 512);
}